// round 16
// baseline (speedup 1.0000x reference)
#include <cuda_runtime.h>
#include <cuda_bf16.h>
#include <cuda_fp16.h>
#include <math.h>
#include <stdint.h>

// ---------------- problem constants ----------------
#define T_TREES   150
#define NPT       341
#define NN        (T_TREES*NPT)
#define HID       256
#define IOUW      768
#define VOCAB     10000
#define LEAF_LOC0 85
#define LPT       256
#define NLEAF     (T_TREES*LPT)
#define NINT      (T_TREES*64)

typedef __nv_bfloat16 bf16;
typedef unsigned char u8;

// ---------------- scratch ------------------------------------------------------
__device__ u8    g_P8  [2u*VOCAB*IOUW];   // fp8 e4m3 P tables (x32 scaled)
__device__ u8    g_h8  [2u*NN*HID];       // fp8 h (fgate GEMM A operand)
__device__ float g_iou [2u*NINT*IOUW];
__device__ float g_c   [2u*NN*HID];
__device__ float g_cs  [2u*NINT*HID];
__device__ bf16  g_hb  [2u*NN*HID];       // bf16 h (child-sum + readout)
__device__ u8    g_UfT8[2u*256*256];      // Uf^T fp8 (x1)
__device__ u8    g_UiT8[2u*768*256];      // Ui^T fp8 (x1)
__device__ u8    g_WiT8[2u*768*256];      // Wi^T fp8 (x16)
__device__ float g_red [2u*T_TREES*8*256];

__device__ __forceinline__ float tanh_fast(float x) {
    float y; asm("tanh.approx.f32 %0, %1;" : "=f"(y) : "f"(x)); return y;
}
__device__ __forceinline__ float sigt(float x) {
    return fmaf(0.5f, tanh_fast(0.5f * x), 0.5f);
}
__device__ __forceinline__ unsigned smem_u32(const void* p) {
    unsigned a;
    asm("{ .reg .u64 t; cvta.to.shared.u64 t, %1; cvt.u32.u64 %0, t; }" : "=r"(a) : "l"(p));
    return a;
}
__device__ __forceinline__ void cp16(unsigned dst, const void* src, int bytes) {
    asm volatile("cp.async.ca.shared.global [%0], [%1], 16, %2;"
                 :: "r"(dst), "l"(src), "r"(bytes) : "memory");
}
#define LDSM4(r0,r1,r2,r3,addr) \
    asm volatile("ldmatrix.sync.aligned.m8n8.x4.shared.b16 {%0,%1,%2,%3}, [%4];" \
        : "=r"(r0),"=r"(r1),"=r"(r2),"=r"(r3) : "r"(addr))

__device__ __forceinline__ unsigned addb2(unsigned x, unsigned y) {
    __nv_bfloat162 a = *(__nv_bfloat162*)&x, b = *(__nv_bfloat162*)&y;
    __nv_bfloat162 r = __hadd2(a, b);
    return *(unsigned*)&r;
}
__device__ __forceinline__ uint4 addb2_4(uint4 a, uint4 b) {
    uint4 r;
    r.x = addb2(a.x, b.x); r.y = addb2(a.y, b.y);
    r.z = addb2(a.z, b.z); r.w = addb2(a.w, b.w);
    return r;
}
__device__ __forceinline__ uint4 bsum4(const bf16* p) {
    uint4 a = *(const uint4*)p, b = *(const uint4*)(p + 256);
    uint4 c = *(const uint4*)(p + 512), d = *(const uint4*)(p + 768);
    return addb2_4(addb2_4(a, b), addb2_4(c, d));
}
__device__ __forceinline__ __half2 fp8_to_h2(unsigned short w) {
    unsigned r;
    asm("cvt.rn.f16x2.e4m3x2 %0, %1;" : "=r"(r) : "h"(w));
    return *(__half2*)&r;
}
__device__ __forceinline__ unsigned short f2_to_fp8(float v0, float v1) {
    unsigned short w;
    asm("cvt.rn.satfinite.e4m3x2.f32 %0, %1, %2;" : "=h"(w) : "f"(v1), "f"(v0));
    return w;
}
// 8 bf16 (uint4) -> 8 fp8 (uint2)
__device__ __forceinline__ uint2 bf8_to_fp8(uint4 t) {
    float2 f0 = __bfloat1622float2(*(__nv_bfloat162*)&t.x);
    float2 f1 = __bfloat1622float2(*(__nv_bfloat162*)&t.y);
    float2 f2 = __bfloat1622float2(*(__nv_bfloat162*)&t.z);
    float2 f3 = __bfloat1622float2(*(__nv_bfloat162*)&t.w);
    unsigned short w0 = f2_to_fp8(f0.x, f0.y), w1 = f2_to_fp8(f1.x, f1.y);
    unsigned short w2 = f2_to_fp8(f2.x, f2.y), w3 = f2_to_fp8(f3.x, f3.y);
    uint2 r;
    r.x = (unsigned)w0 | ((unsigned)w1 << 16);
    r.y = (unsigned)w2 | ((unsigned)w3 << 16);
    return r;
}
// 8 fp32 -> 8 fp8 (uint2), scaled
__device__ __forceinline__ uint2 f8_to_fp8(const float* s, float sc) {
    unsigned short w0 = f2_to_fp8(s[0]*sc, s[1]*sc), w1 = f2_to_fp8(s[2]*sc, s[3]*sc);
    unsigned short w2 = f2_to_fp8(s[4]*sc, s[5]*sc), w3 = f2_to_fp8(s[6]*sc, s[7]*sc);
    uint2 r;
    r.x = (unsigned)w0 | ((unsigned)w1 << 16);
    r.y = (unsigned)w2 | ((unsigned)w3 << 16);
    return r;
}

// ---------------- fp8 mma GEMM body (BK=64 fp8 = 64B chunks, 4 chunks) ----------
// mode: 1 node-mapped fp8 rows; 2 bf16 4-child-sum -> fp8 inline; 3 fp32 -> fp8 inline
// epi : 0 fp32 store; 1 fgate sig*c -> 4-row reduce -> cs; 4 fp8 store (x oscale)
struct GemmArgs {
    const void* A; const u8* Bt; const float* bias; const float* Cst;
    void* Out; int M; int Ntot; int start; int rpt; int mode; int epi;
    float ascale; float oscale;
};
__device__ __forceinline__ int rmap(const GemmArgs& a, int r) {
    return (a.mode == 1) ? ((r / a.rpt) * NPT + a.start + (r % a.rpt)) : r;
}

#define STRB 80u

__device__ __forceinline__ void gemm_body(const GemmArgs& a, int bx, int by) {
    __shared__ __align__(16) char As[2][128 * STRB];
    __shared__ __align__(16) char Bs[2][128 * STRB];
    int tid = threadIdx.x, lane = tid & 31, wid = tid >> 5;
    int wm = wid >> 2, wn = wid & 3;
    int qr = lane >> 2, qc = lane & 3;
    int m0 = by * 128, n0 = bx * 128;

    int lrow = tid >> 1, lhalf = tid & 1;   // thread covers 32 of 64 elems per chunk
    int gr = m0 + lrow;
    const u8*    Ap8 = nullptr;
    const bf16*  Abf = nullptr;
    const float* Afp = nullptr;
    if (gr < a.M) {
        if (a.mode == 1)
            Ap8 = (const u8*)a.A + (size_t)rmap(a, gr) * 256 + lhalf * 32;
        else if (a.mode == 2)
            Abf = (const bf16*)a.A + (size_t)((gr / a.rpt) * NPT + a.start + 4 * (gr % a.rpt)) * 256 + lhalf * 32;
        else
            Afp = (const float*)a.A + (size_t)gr * 256 + lhalf * 32;
    }
    const u8* Ap8Safe = Ap8 ? Ap8 : (const u8*)a.A;
    int abytes = Ap8 ? 16 : 0;
    const u8* Bp = a.Bt + (size_t)(n0 + lrow) * 256 + lhalf * 32;
    unsigned dAl = smem_u32(As) + lrow * STRB + lhalf * 32u;
    unsigned dBl = smem_u32(Bs) + lrow * STRB + lhalf * 32u;
    char* dAst = &As[0][lrow * STRB + lhalf * 32];
    const unsigned stageB = 128u * STRB;

    unsigned aRowOff = (((lane >> 3) & 1) * 8 + (lane & 7)) * STRB + (lane >> 4) * 16u;
    unsigned bRowOff = (((lane >> 4) << 3) + (lane & 7)) * STRB + ((lane >> 3) & 1) * 16u;
    unsigned aBase = smem_u32(As) + (wm * 64) * STRB + aRowOff;
    unsigned bBase = smem_u32(Bs) + (wn * 32) * STRB + bRowOff;

    float acc[4][4][4];
    #pragma unroll
    for (int mt = 0; mt < 4; mt++)
        #pragma unroll
        for (int nt = 0; nt < 4; nt++)
            #pragma unroll
            for (int i = 0; i < 4; i++) acc[mt][nt][i] = 0.f;

    // ---- A fill helper per chunk ----
    auto fillA = [&](int kc, int st) {
        if (a.mode == 1) {
            cp16(dAl + st * stageB,      Ap8Safe + kc,      abytes);
            cp16(dAl + st * stageB + 16, Ap8Safe + kc + 16, abytes);
        } else if (a.mode == 2) {
            uint2 z2 = make_uint2(0, 0);
            uint2 r0 = Abf ? bf8_to_fp8(bsum4(Abf + kc))      : z2;
            uint2 r1 = Abf ? bf8_to_fp8(bsum4(Abf + kc + 8))  : z2;
            uint2 r2 = Abf ? bf8_to_fp8(bsum4(Abf + kc + 16)) : z2;
            uint2 r3 = Abf ? bf8_to_fp8(bsum4(Abf + kc + 24)) : z2;
            uint4 o0 = make_uint4(r0.x, r0.y, r1.x, r1.y);
            uint4 o1 = make_uint4(r2.x, r2.y, r3.x, r3.y);
            *(uint4*)(dAst + st * (int)stageB)      = o0;
            *(uint4*)(dAst + st * (int)stageB + 16) = o1;
        } else {
            uint2 z2 = make_uint2(0, 0);
            float buf[8];
            uint2 r0 = z2, r1 = z2, r2 = z2, r3 = z2;
            if (Afp) {
                *(float4*)buf = *(const float4*)(Afp + kc);
                *(float4*)(buf+4) = *(const float4*)(Afp + kc + 4);
                r0 = f8_to_fp8(buf, a.ascale);
                *(float4*)buf = *(const float4*)(Afp + kc + 8);
                *(float4*)(buf+4) = *(const float4*)(Afp + kc + 12);
                r1 = f8_to_fp8(buf, a.ascale);
                *(float4*)buf = *(const float4*)(Afp + kc + 16);
                *(float4*)(buf+4) = *(const float4*)(Afp + kc + 20);
                r2 = f8_to_fp8(buf, a.ascale);
                *(float4*)buf = *(const float4*)(Afp + kc + 24);
                *(float4*)(buf+4) = *(const float4*)(Afp + kc + 28);
                r3 = f8_to_fp8(buf, a.ascale);
            }
            uint4 o0 = make_uint4(r0.x, r0.y, r1.x, r1.y);
            uint4 o1 = make_uint4(r2.x, r2.y, r3.x, r3.y);
            *(uint4*)(dAst + st * (int)stageB)      = o0;
            *(uint4*)(dAst + st * (int)stageB + 16) = o1;
        }
    };

    // prologue: stage 0 <- chunk 0
    fillA(0, 0);
    cp16(dBl,      Bp,      16);
    cp16(dBl + 16, Bp + 16, 16);
    asm volatile("cp.async.commit_group;" ::: "memory");

    #pragma unroll
    for (int c = 0; c < 4; c++) {
        if (c < 3) {
            int st = (c + 1) & 1;
            int kc = (c + 1) * 64;
            fillA(kc, st);
            cp16(dBl + st * stageB,      Bp + kc,      16);
            cp16(dBl + st * stageB + 16, Bp + kc + 16, 16);
            asm volatile("cp.async.commit_group;" ::: "memory");
            asm volatile("cp.async.wait_group 1;" ::: "memory");
        } else {
            asm volatile("cp.async.wait_group 0;" ::: "memory");
        }
        __syncthreads();

        unsigned aS = aBase + (c & 1) * stageB;
        unsigned bS = bBase + (c & 1) * stageB;
        #pragma unroll
        for (int ks = 0; ks < 2; ks++) {        // two k32 steps per 64B chunk
            unsigned koff = ks * 32u;
            unsigned af[4][4], bfr[4][2];
            #pragma unroll
            for (int mt = 0; mt < 4; mt++)
                LDSM4(af[mt][0], af[mt][1], af[mt][2], af[mt][3],
                      aS + mt * 16u * STRB + koff);
            LDSM4(bfr[0][0], bfr[0][1], bfr[1][0], bfr[1][1], bS + koff);
            LDSM4(bfr[2][0], bfr[2][1], bfr[3][0], bfr[3][1], bS + 16u * STRB + koff);
            #pragma unroll
            for (int mt = 0; mt < 4; mt++)
                #pragma unroll
                for (int nt = 0; nt < 4; nt++) {
                    float* d = acc[mt][nt];
                    asm volatile(
                        "mma.sync.aligned.m16n8k32.row.col.f32.e4m3.e4m3.f32 "
                        "{%0,%1,%2,%3}, {%4,%5,%6,%7}, {%8,%9}, {%0,%1,%2,%3};"
                        : "+f"(d[0]), "+f"(d[1]), "+f"(d[2]), "+f"(d[3])
                        : "r"(af[mt][0]), "r"(af[mt][1]), "r"(af[mt][2]), "r"(af[mt][3]),
                          "r"(bfr[nt][0]), "r"(bfr[nt][1]));
                }
        }
        __syncthreads();
    }

    if (a.epi == 1) {
        int base0 = m0 + wm * 64;
        #pragma unroll
        for (int mt = 0; mt < 4; mt++) {
            #pragma unroll
            for (int half = 0; half < 2; half++) {
                int gb = base0 + mt * 16 + half * 8 + ((lane & 16) >> 2);
                bool valid = gb < a.M;
                int r = gb + ((lane >> 2) & 3);
                int rr = valid ? rmap(a, r) : 0;
                #pragma unroll
                for (int nt = 0; nt < 4; nt++) {
                    int col = n0 + wn * 32 + nt * 8 + qc * 2;
                    float o0 = 0.f, o1 = 0.f;
                    if (valid) {
                        const float* cp = a.Cst + (size_t)rr * 256 + col;
                        o0 = sigt(acc[mt][nt][half*2+0] + __ldg(&a.bias[col]))     * cp[0];
                        o1 = sigt(acc[mt][nt][half*2+1] + __ldg(&a.bias[col + 1])) * cp[1];
                    }
                    o0 += __shfl_xor_sync(0xffffffffu, o0, 4);
                    o0 += __shfl_xor_sync(0xffffffffu, o0, 8);
                    o1 += __shfl_xor_sync(0xffffffffu, o1, 4);
                    o1 += __shfl_xor_sync(0xffffffffu, o1, 8);
                    if (valid && (lane & 12) == 0) {
                        int pr = gb >> 2;
                        *(float2*)((float*)a.Out + (size_t)pr * 256 + col) = make_float2(o0, o1);
                    }
                }
            }
        }
    } else {
        #pragma unroll
        for (int mt = 0; mt < 4; mt++) {
            #pragma unroll
            for (int half = 0; half < 2; half++) {
                int r = m0 + wm * 64 + mt * 16 + qr + half * 8;
                if (r >= a.M) continue;
                #pragma unroll
                for (int nt = 0; nt < 4; nt++) {
                    int col = n0 + wn * 32 + nt * 8 + qc * 2;
                    float v0 = acc[mt][nt][half * 2 + 0];
                    float v1 = acc[mt][nt][half * 2 + 1];
                    if (a.epi == 4) {
                        unsigned short w = f2_to_fp8(v0 * a.oscale, v1 * a.oscale);
                        *(unsigned short*)((u8*)a.Out + (size_t)r * a.Ntot + col) = w;
                    } else {
                        *(float2*)((float*)a.Out + (size_t)r * a.Ntot + col) = make_float2(v0, v1);
                    }
                }
            }
        }
    }
}

__global__ __launch_bounds__(256, 2)
void mma_gemm(GemmArgs a0, GemmArgs a1) {
    gemm_body(blockIdx.z ? a1 : a0, blockIdx.x, blockIdx.y);
}

__global__ __launch_bounds__(256, 2)
void level_gemm(GemmArgs f0, GemmArgs f1, GemmArgs u0, GemmArgs u1, int nf) {
    int bid = blockIdx.x;
    if (bid < nf) {
        gemm_body(blockIdx.z ? f1 : f0, bid & 1, bid >> 1);
    } else {
        int r2 = bid - nf;
        gemm_body(blockIdx.z ? u1 : u0, r2 % 6, r2 / 6);
    }
}

// ---------------- weight transpose: S[256,N] fp32 -> D[N,256] fp8 (scaled) ------
struct TPair { const float* s; u8* d; int n; float sc; };
__global__ void transpose_k(TPair p0, TPair p1, TPair p2, TPair p3, TPair p4, TPair p5) {
    TPair p;
    switch (blockIdx.z) {
        case 0: p = p0; break; case 1: p = p1; break; case 2: p = p2; break;
        case 3: p = p3; break; case 4: p = p4; break; default: p = p5; break;
    }
    int x0 = blockIdx.x * 32;
    if (x0 >= p.n) return;
    int y0 = blockIdx.y * 32;
    __shared__ float t[32][33];
    #pragma unroll
    for (int s = 0; s < 32; s += 8)
        t[threadIdx.y + s][threadIdx.x] = p.s[(size_t)(y0 + threadIdx.y + s) * p.n + x0 + threadIdx.x];
    __syncthreads();
    // write: 16 x-threads each emit a fp8 pair along contiguous K
    if (threadIdx.x < 16) {
        #pragma unroll
        for (int s = 0; s < 32; s += 8) {
            float v0 = t[2 * threadIdx.x][threadIdx.y + s] * p.sc;
            float v1 = t[2 * threadIdx.x + 1][threadIdx.y + s] * p.sc;
            unsigned short w = f2_to_fp8(v0, v1);
            *(unsigned short*)(p.d + (size_t)(x0 + threadIdx.y + s) * 256 + y0 + 2 * threadIdx.x) = w;
        }
    }
}

// ------- warp-per-leaf: fp8 gather of 8 P rows, f16 accumulate -> activation -----
__global__ __launch_bounds__(256, 5)
void leaf_act_kernel(const int* __restrict__ nf1, const int* __restrict__ nf2,
                     const float* __restrict__ bi1, const float* __restrict__ bi2) {
    int b = blockIdx.z;
    const int* nf = b ? nf2 : nf1;
    const float* bias = b ? bi2 : bi1;
    int warp = threadIdx.x >> 5, lane = threadIdx.x & 31;
    int leaf = blockIdx.x * 8 + warp;
    int tree = leaf >> 8, ll = leaf & 255;
    int gnode = tree * NPT + LEAF_LOC0 + ll;
    int tok = (lane < 8) ? nf[gnode * 8 + lane] : 0;
    unsigned toks[8];
    #pragma unroll
    for (int s = 0; s < 8; s++)
        toks[s] = (unsigned)__shfl_sync(0xffffffffu, tok, s) * 96u;

    const uint2* P = (const uint2*)(g_P8 + (size_t)b * VOCAB * IOUW);
    __half2 acc[3][4];
    #pragma unroll
    for (int k = 0; k < 3; k++) {
        unsigned w = lane + 32u * k;
        #pragma unroll
        for (int p = 0; p < 4; p++) acc[k][p] = __half2(__float2half(0.f), __float2half(0.f));
        #pragma unroll
        for (int s = 0; s < 8; s++) {
            uint2 v = __ldg(P + toks[s] + w);
            acc[k][0] = __hadd2(acc[k][0], fp8_to_h2((unsigned short)(v.x & 0xffffu)));
            acc[k][1] = __hadd2(acc[k][1], fp8_to_h2((unsigned short)(v.x >> 16)));
            acc[k][2] = __hadd2(acc[k][2], fp8_to_h2((unsigned short)(v.y & 0xffffu)));
            acc[k][3] = __hadd2(acc[k][3], fp8_to_h2((unsigned short)(v.y >> 16)));
        }
    }

    const float SC = 0.125f / 32.f;
    int col0 = lane * 8;
    float fi[8], fo[8], fu[8];
    #pragma unroll
    for (int p = 0; p < 4; p++) {
        float2 xi = __half22float2(acc[0][p]);
        float2 xo = __half22float2(acc[1][p]);
        float2 xu = __half22float2(acc[2][p]);
        fi[2*p] = xi.x; fi[2*p+1] = xi.y;
        fo[2*p] = xo.x; fo[2*p+1] = xo.y;
        fu[2*p] = xu.x; fu[2*p+1] = xu.y;
    }
    float4 bi0 = *(const float4*)&bias[col0],       bi1v = *(const float4*)&bias[col0 + 4];
    float4 bo0 = *(const float4*)&bias[256 + col0], bo1v = *(const float4*)&bias[256 + col0 + 4];
    float4 bu0 = *(const float4*)&bias[512 + col0], bu1v = *(const float4*)&bias[512 + col0 + 4];
    float bI[8] = {bi0.x,bi0.y,bi0.z,bi0.w,bi1v.x,bi1v.y,bi1v.z,bi1v.w};
    float bO[8] = {bo0.x,bo0.y,bo0.z,bo0.w,bo1v.x,bo1v.y,bo1v.z,bo1v.w};
    float bU[8] = {bu0.x,bu0.y,bu0.z,bu0.w,bu1v.x,bu1v.y,bu1v.z,bu1v.w};

    float cr[8], hr[8];
    #pragma unroll
    for (int k = 0; k < 8; k++) {
        cr[k] = sigt(fi[k] * SC + bI[k]) * tanh_fast(fu[k] * SC + bU[k]);
        hr[k] = sigt(fo[k] * SC + bO[k]) * tanh_fast(cr[k]);
    }
    size_t base = (size_t)b * NN * HID + (size_t)gnode * HID + col0;
    uint4 hout;
    __nv_bfloat162 h01 = __floats2bfloat162_rn(hr[0], hr[1]);
    __nv_bfloat162 h23 = __floats2bfloat162_rn(hr[2], hr[3]);
    __nv_bfloat162 h45 = __floats2bfloat162_rn(hr[4], hr[5]);
    __nv_bfloat162 h67 = __floats2bfloat162_rn(hr[6], hr[7]);
    hout.x = *(unsigned*)&h01; hout.y = *(unsigned*)&h23;
    hout.z = *(unsigned*)&h45; hout.w = *(unsigned*)&h67;
    *(uint4*)&g_hb[base] = hout;
    *(float4*)&g_c[base]     = make_float4(cr[0], cr[1], cr[2], cr[3]);
    *(float4*)&g_c[base + 4] = make_float4(cr[4], cr[5], cr[6], cr[7]);
    uint2 h8 = f8_to_fp8(hr, 1.f);
    *(uint2*)&g_h8[base] = h8;
}

// ------- act: iou row + single cs row, fp32, writes h (bf16 + fp8) ---------------
__global__ __launch_bounds__(256)
void act_kernel(const float* __restrict__ bi1, const float* __restrict__ bi2,
                int Mp, int start, int rpt) {
    int b = blockIdx.z;
    const float* bias = b ? bi2 : bi1;
    int r = blockIdx.x * 4 + (threadIdx.x >> 6);
    if (r >= Mp) return;
    int j = (threadIdx.x & 63) * 4;
    int tree = r / rpt, lp = r % rpt;
    const float* iou = g_iou + (size_t)b * NINT * IOUW + (size_t)r * IOUW;
    float4 iv = *(const float4*)(iou + j);
    float4 ov = *(const float4*)(iou + 256 + j);
    float4 uv = *(const float4*)(iou + 512 + j);
    float4 bi = *(const float4*)(bias + j);
    float4 bo = *(const float4*)(bias + 256 + j);
    float4 bu = *(const float4*)(bias + 512 + j);
    float4 cs4 = *(const float4*)(g_cs + (size_t)b * NINT * HID + (size_t)r * HID + j);
    float cs[4] = {cs4.x, cs4.y, cs4.z, cs4.w};
    float ivv[4] = {iv.x+bi.x, iv.y+bi.y, iv.z+bi.z, iv.w+bi.w};
    float ovv[4] = {ov.x+bo.x, ov.y+bo.y, ov.z+bo.z, ov.w+bo.w};
    float uvv[4] = {uv.x+bu.x, uv.y+bu.y, uv.z+bu.z, uv.w+bu.w};
    float cr[4], hr[4];
    #pragma unroll
    for (int k = 0; k < 4; k++) {
        cr[k] = sigt(ivv[k]) * tanh_fast(uvv[k]) + cs[k];
        hr[k] = sigt(ovv[k]) * tanh_fast(cr[k]);
    }
    int g = tree * NPT + start + lp;
    size_t base = (size_t)b * NN * HID + (size_t)g * HID + j;
    uint2 hb2;
    __nv_bfloat162 h01 = __floats2bfloat162_rn(hr[0], hr[1]);
    __nv_bfloat162 h23 = __floats2bfloat162_rn(hr[2], hr[3]);
    hb2.x = *(unsigned*)&h01; hb2.y = *(unsigned*)&h23;
    *(uint2*)&g_hb[base] = hb2;
    *(float4*)&g_c[base] = make_float4(cr[0], cr[1], cr[2], cr[3]);
    unsigned short w0 = f2_to_fp8(hr[0], hr[1]);
    unsigned short w1 = f2_to_fp8(hr[2], hr[3]);
    *(unsigned*)&g_h8[base] = (unsigned)w0 | ((unsigned)w1 << 16);
}

// ------- readout phase 1: 8 partial sums per tree --------------------------------
__global__ __launch_bounds__(128)
void readout_part(void) {
    int t = blockIdx.x, part = blockIdx.y, b = blockIdx.z;
    int j = threadIdx.x;
    int n0 = part * 43;
    int n1 = (n0 + 43 < NPT) ? n0 + 43 : NPT;
    const unsigned* hp = (const unsigned*)(g_hb + (size_t)b * NN * HID
                                           + (size_t)t * NPT * HID) + j;
    float s0 = 0.f, s1 = 0.f;
    for (int n = n0; n < n1; n++) {
        float2 v = __bfloat1622float2(*(__nv_bfloat162*)&hp[n * 128]);
        s0 += v.x; s1 += v.y;
    }
    float* dst = g_red + (((size_t)b * T_TREES + t) * 8 + part) * 256 + 2 * j;
    *(float2*)dst = make_float2(s0, s1);
}

// ------- readout phase 2 ---------------------------------------------------------
__global__ __launch_bounds__(256)
void readout_fin(const float* __restrict__ Wf, const float* __restrict__ bf,
                 float* __restrict__ out) {
    int t = blockIdx.x;
    int br = threadIdx.x >> 7;
    int j = threadIdx.x & 127;
    const float* rp = g_red + (((size_t)br * T_TREES + t) * 8) * 256 + 2 * j;
    float s0 = 0.f, s1 = 0.f;
    #pragma unroll
    for (int p = 0; p < 8; p++) {
        float2 v = *(const float2*)(rp + p * 256);
        s0 += v.x; s1 += v.y;
    }
    float m0 = fmaxf(s0 * (1.0f / NPT), 0.f);
    float m1 = fmaxf(s1 * (1.0f / NPT), 0.f);
    int col0 = br * 256 + 2 * j;
    float p0 = m0 * Wf[col0 * 2 + 0] + m1 * Wf[(col0 + 1) * 2 + 0];
    float p1 = m0 * Wf[col0 * 2 + 1] + m1 * Wf[(col0 + 1) * 2 + 1];
    __shared__ float sm0[256], sm1[256];
    sm0[threadIdx.x] = p0; sm1[threadIdx.x] = p1; __syncthreads();
    for (int s = 128; s > 0; s >>= 1) {
        if (threadIdx.x < s) {
            sm0[threadIdx.x] += sm0[threadIdx.x + s];
            sm1[threadIdx.x] += sm1[threadIdx.x + s];
        }
        __syncthreads();
    }
    if (threadIdx.x == 0) {
        float l0 = sm0[0] + bf[0], l1 = sm1[0] + bf[1];
        l0 = (l0 >= 0.f) ? l0 : 0.01f * l0;
        l1 = (l1 >= 0.f) ? l1 : 0.01f * l1;
        float mx = fmaxf(l0, l1);
        float e0 = __expf(l0 - mx), e1 = __expf(l1 - mx);
        float inv = 1.0f / (e0 + e1);
        out[t * 2 + 0] = e0 * inv;
        out[t * 2 + 1] = e1 * inv;
    }
}

// -------------------------------- launch --------------------------------------
extern "C" void kernel_launch(void* const* d_in, const int* in_sizes, int n_in,
                              void* d_out, int out_size) {
    const int*   nf1   = (const int*)  d_in[0];
    const int*   nf2   = (const int*)  d_in[1];
    const float* emb1  = (const float*)d_in[2];
    const float* emb2  = (const float*)d_in[3];
    const float* Wiou1 = (const float*)d_in[4];
    const float* Wiou2 = (const float*)d_in[5];
    const float* Uiou1 = (const float*)d_in[6];
    const float* Uiou2 = (const float*)d_in[7];
    const float* UfW1  = (const float*)d_in[8];
    const float* Ufb1  = (const float*)d_in[9];
    const float* UfW2  = (const float*)d_in[10];
    const float* Ufb2  = (const float*)d_in[11];
    const float* biou1 = (const float*)d_in[12];
    const float* biou2 = (const float*)d_in[13];
    const float* Wf    = (const float*)d_in[14];
    const float* bf    = (const float*)d_in[15];
    float* out = (float*)d_out;

    float *iouS, *c, *cs;
    u8 *P8, *h8, *UfT8, *UiT8, *WiT8;
    bf16 *hb;
    cudaGetSymbolAddress((void**)&P8,   g_P8);
    cudaGetSymbolAddress((void**)&h8,   g_h8);
    cudaGetSymbolAddress((void**)&iouS, g_iou);
    cudaGetSymbolAddress((void**)&c,    g_c);
    cudaGetSymbolAddress((void**)&cs,   g_cs);
    cudaGetSymbolAddress((void**)&hb,   g_hb);
    cudaGetSymbolAddress((void**)&UfT8, g_UfT8);
    cudaGetSymbolAddress((void**)&UiT8, g_UiT8);
    cudaGetSymbolAddress((void**)&WiT8, g_WiT8);

    const size_t Poff = (size_t)VOCAB * IOUW;
    const size_t Hoff = (size_t)NN * HID;
    const size_t Soff = (size_t)NINT * HID;
    const size_t Ioff = (size_t)NINT * IOUW;

    // weights -> fp8 [N,K]: Uf x1, Ui x1, Wi x16
    transpose_k<<<dim3(24, 8, 6), dim3(32, 8)>>>(
        TPair{UfW1, UfT8, 256, 1.f},          TPair{UfW2, UfT8 + 256*256, 256, 1.f},
        TPair{Uiou1, UiT8, 768, 1.f},         TPair{Uiou2, UiT8 + 768*256, 768, 1.f},
        TPair{Wiou1, WiT8, 768, 16.f},        TPair{Wiou2, WiT8 + 768*256, 768, 16.f});

    // P tables: emb(fp32 x32 inline) @ Wi(fp8 x16) -> fp8 (stored x32: oscale = 32/512)
    {
        GemmArgs a0{emb1, WiT8,           nullptr, nullptr, P8,        VOCAB, IOUW, 0, 1, 3, 4, 32.f, 0.0625f};
        GemmArgs a1{emb2, WiT8 + 768*256, nullptr, nullptr, P8 + Poff, VOCAB, IOUW, 0, 1, 3, 4, 32.f, 0.0625f};
        mma_gemm<<<dim3(IOUW/128, (VOCAB + 127)/128, 2), 256>>>(a0, a1);
    }
    leaf_act_kernel<<<dim3(NLEAF/8, 1, 2), 256>>>(nf1, nf2, biou1, biou2);

    const int ps_[4]   = {21, 5, 1, 0};
    const int pcnt_[4] = {64, 16, 4, 1};
    const int cs_[4]   = {85, 21, 5, 1};
    const int ccnt_[4] = {256, 64, 16, 4};

    for (int L = 0; L < 4; L++) {
        int Mc = T_TREES * ccnt_[L];
        int Mp = T_TREES * pcnt_[L];
        int nf = 2 * ((Mc + 127) / 128);
        int nu = 6 * ((Mp + 127) / 128);
        GemmArgs f0{h8,        UfT8,           Ufb1, c,        cs,        Mc, 256, cs_[L], ccnt_[L], 1, 1, 1.f, 1.f};
        GemmArgs f1{h8 + Hoff, UfT8 + 256*256, Ufb2, c + Hoff, cs + Soff, Mc, 256, cs_[L], ccnt_[L], 1, 1, 1.f, 1.f};
        GemmArgs u0{hb,        UiT8,           nullptr, nullptr, iouS,        Mp, IOUW, cs_[L], pcnt_[L], 2, 0, 1.f, 1.f};
        GemmArgs u1{hb + Hoff, UiT8 + 768*256, nullptr, nullptr, iouS + Ioff, Mp, IOUW, cs_[L], pcnt_[L], 2, 0, 1.f, 1.f};
        level_gemm<<<dim3(nf + nu, 1, 2), 256>>>(f0, f1, u0, u1, nf);
        act_kernel<<<dim3((Mp + 3)/4, 1, 2), 256>>>(biou1, biou2, Mp, ps_[L], pcnt_[L]);
    }

    readout_part<<<dim3(T_TREES, 8, 2), 128>>>();
    readout_fin<<<T_TREES, 256>>>(Wf, bf, out);
}

// round 17
// speedup vs baseline: 1.0940x; 1.0940x over previous
#include <cuda_runtime.h>
#include <cuda_bf16.h>
#include <cuda_fp16.h>
#include <math.h>
#include <stdint.h>

// ---------------- problem constants ----------------
#define T_TREES   150
#define NPT       341
#define NN        (T_TREES*NPT)
#define HID       256
#define IOUW      768
#define VOCAB     10000
#define LEAF_LOC0 85
#define LPT       256
#define NLEAF     (T_TREES*LPT)
#define NINT      (T_TREES*64)

typedef __nv_bfloat16 bf16;
typedef unsigned char u8;

// ---------------- scratch ------------------------------------------------------
__device__ u8    g_P8  [2u*VOCAB*IOUW];   // fp8 e4m3 P tables (x32 scaled)
__device__ u8    g_h8  [2u*NN*HID];       // fp8 h (fgate GEMM A operand)
__device__ float g_iou [2u*NINT*IOUW];
__device__ float g_c   [2u*NN*HID];
__device__ float g_cs  [2u*NINT*HID];
__device__ bf16  g_hb  [2u*NN*HID];       // bf16 h (child-sum + readout)
__device__ u8    g_UfT8[2u*256*256];      // Uf^T fp8 (x1)
__device__ u8    g_UiT8[2u*768*256];      // Ui^T fp8 (x1)
__device__ u8    g_WiT8[2u*768*256];      // Wi^T fp8 (x16)
__device__ float g_red [2u*T_TREES*8*256];

__device__ __forceinline__ float tanh_fast(float x) {
    float y; asm("tanh.approx.f32 %0, %1;" : "=f"(y) : "f"(x)); return y;
}
__device__ __forceinline__ float sigt(float x) {
    return fmaf(0.5f, tanh_fast(0.5f * x), 0.5f);
}
__device__ __forceinline__ unsigned smem_u32(const void* p) {
    unsigned a;
    asm("{ .reg .u64 t; cvta.to.shared.u64 t, %1; cvt.u32.u64 %0, t; }" : "=r"(a) : "l"(p));
    return a;
}
__device__ __forceinline__ void cp16(unsigned dst, const void* src, int bytes) {
    asm volatile("cp.async.ca.shared.global [%0], [%1], 16, %2;"
                 :: "r"(dst), "l"(src), "r"(bytes) : "memory");
}
#define LDSM4(r0,r1,r2,r3,addr) \
    asm volatile("ldmatrix.sync.aligned.m8n8.x4.shared.b16 {%0,%1,%2,%3}, [%4];" \
        : "=r"(r0),"=r"(r1),"=r"(r2),"=r"(r3) : "r"(addr))

__device__ __forceinline__ unsigned addb2(unsigned x, unsigned y) {
    __nv_bfloat162 a = *(__nv_bfloat162*)&x, b = *(__nv_bfloat162*)&y;
    __nv_bfloat162 r = __hadd2(a, b);
    return *(unsigned*)&r;
}
__device__ __forceinline__ uint4 addb2_4(uint4 a, uint4 b) {
    uint4 r;
    r.x = addb2(a.x, b.x); r.y = addb2(a.y, b.y);
    r.z = addb2(a.z, b.z); r.w = addb2(a.w, b.w);
    return r;
}
__device__ __forceinline__ uint4 bsum4(const bf16* p) {
    uint4 a = *(const uint4*)p, b = *(const uint4*)(p + 256);
    uint4 c = *(const uint4*)(p + 512), d = *(const uint4*)(p + 768);
    return addb2_4(addb2_4(a, b), addb2_4(c, d));
}
__device__ __forceinline__ __half2 fp8_to_h2(unsigned short w) {
    unsigned r;
    asm("cvt.rn.f16x2.e4m3x2 %0, %1;" : "=r"(r) : "h"(w));
    return *(__half2*)&r;
}
__device__ __forceinline__ unsigned short f2_to_fp8(float v0, float v1) {
    unsigned short w;
    asm("cvt.rn.satfinite.e4m3x2.f32 %0, %1, %2;" : "=h"(w) : "f"(v1), "f"(v0));
    return w;
}
// 8 bf16 (uint4) -> 8 fp8 (uint2)
__device__ __forceinline__ uint2 bf8_to_fp8(uint4 t) {
    float2 f0 = __bfloat1622float2(*(__nv_bfloat162*)&t.x);
    float2 f1 = __bfloat1622float2(*(__nv_bfloat162*)&t.y);
    float2 f2 = __bfloat1622float2(*(__nv_bfloat162*)&t.z);
    float2 f3 = __bfloat1622float2(*(__nv_bfloat162*)&t.w);
    unsigned short w0 = f2_to_fp8(f0.x, f0.y), w1 = f2_to_fp8(f1.x, f1.y);
    unsigned short w2 = f2_to_fp8(f2.x, f2.y), w3 = f2_to_fp8(f3.x, f3.y);
    uint2 r;
    r.x = (unsigned)w0 | ((unsigned)w1 << 16);
    r.y = (unsigned)w2 | ((unsigned)w3 << 16);
    return r;
}
// 8 fp32 -> 8 fp8 (uint2), scaled
__device__ __forceinline__ uint2 f8_to_fp8(const float* s, float sc) {
    unsigned short w0 = f2_to_fp8(s[0]*sc, s[1]*sc), w1 = f2_to_fp8(s[2]*sc, s[3]*sc);
    unsigned short w2 = f2_to_fp8(s[4]*sc, s[5]*sc), w3 = f2_to_fp8(s[6]*sc, s[7]*sc);
    uint2 r;
    r.x = (unsigned)w0 | ((unsigned)w1 << 16);
    r.y = (unsigned)w2 | ((unsigned)w3 << 16);
    return r;
}

// ---------------- fp8 mma GEMM body, f16 accumulators ---------------------------
// mode: 1 node-mapped fp8 rows; 2 bf16 4-child-sum -> fp8 inline; 3 fp32 -> fp8 inline
// epi : 0 fp32 store; 1 fgate sig*c -> 4-row reduce -> cs; 4 fp8 store (x oscale)
struct GemmArgs {
    const void* A; const u8* Bt; const float* bias; const float* Cst;
    void* Out; int M; int Ntot; int start; int rpt; int mode; int epi;
    float ascale; float oscale;
};
__device__ __forceinline__ int rmap(const GemmArgs& a, int r) {
    return (a.mode == 1) ? ((r / a.rpt) * NPT + a.start + (r % a.rpt)) : r;
}

#define STRB 80u

__device__ __forceinline__ void gemm_body(const GemmArgs& a, int bx, int by) {
    __shared__ __align__(16) char As[2][128 * STRB];
    __shared__ __align__(16) char Bs[2][128 * STRB];
    int tid = threadIdx.x, lane = tid & 31, wid = tid >> 5;
    int wm = wid >> 2, wn = wid & 3;
    int qr = lane >> 2, qc = lane & 3;
    int m0 = by * 128, n0 = bx * 128;

    int lrow = tid >> 1, lhalf = tid & 1;
    int gr = m0 + lrow;
    const u8*    Ap8 = nullptr;
    const bf16*  Abf = nullptr;
    const float* Afp = nullptr;
    if (gr < a.M) {
        if (a.mode == 1)
            Ap8 = (const u8*)a.A + (size_t)rmap(a, gr) * 256 + lhalf * 32;
        else if (a.mode == 2)
            Abf = (const bf16*)a.A + (size_t)((gr / a.rpt) * NPT + a.start + 4 * (gr % a.rpt)) * 256 + lhalf * 32;
        else
            Afp = (const float*)a.A + (size_t)gr * 256 + lhalf * 32;
    }
    const u8* Ap8Safe = Ap8 ? Ap8 : (const u8*)a.A;
    int abytes = Ap8 ? 16 : 0;
    const u8* Bp = a.Bt + (size_t)(n0 + lrow) * 256 + lhalf * 32;
    unsigned dAl = smem_u32(As) + lrow * STRB + lhalf * 32u;
    unsigned dBl = smem_u32(Bs) + lrow * STRB + lhalf * 32u;
    char* dAst = &As[0][lrow * STRB + lhalf * 32];
    const unsigned stageB = 128u * STRB;

    unsigned aRowOff = (((lane >> 3) & 1) * 8 + (lane & 7)) * STRB + (lane >> 4) * 16u;
    unsigned bRowOff = (((lane >> 4) << 3) + (lane & 7)) * STRB + ((lane >> 3) & 1) * 16u;
    unsigned aBase = smem_u32(As) + (wm * 64) * STRB + aRowOff;
    unsigned bBase = smem_u32(Bs) + (wn * 32) * STRB + bRowOff;

    // f16x2 accumulators: [mt][nt][half] (half0 = rows qr, half1 = rows qr+8)
    unsigned acc[4][4][2];
    #pragma unroll
    for (int mt = 0; mt < 4; mt++)
        #pragma unroll
        for (int nt = 0; nt < 4; nt++) { acc[mt][nt][0] = 0u; acc[mt][nt][1] = 0u; }

    auto fillA = [&](int kc, int st) {
        if (a.mode == 1) {
            cp16(dAl + st * stageB,      Ap8Safe + kc,      abytes);
            cp16(dAl + st * stageB + 16, Ap8Safe + kc + 16, abytes);
        } else if (a.mode == 2) {
            uint2 z2 = make_uint2(0, 0);
            uint2 r0 = Abf ? bf8_to_fp8(bsum4(Abf + kc))      : z2;
            uint2 r1 = Abf ? bf8_to_fp8(bsum4(Abf + kc + 8))  : z2;
            uint2 r2 = Abf ? bf8_to_fp8(bsum4(Abf + kc + 16)) : z2;
            uint2 r3 = Abf ? bf8_to_fp8(bsum4(Abf + kc + 24)) : z2;
            uint4 o0 = make_uint4(r0.x, r0.y, r1.x, r1.y);
            uint4 o1 = make_uint4(r2.x, r2.y, r3.x, r3.y);
            *(uint4*)(dAst + st * (int)stageB)      = o0;
            *(uint4*)(dAst + st * (int)stageB + 16) = o1;
        } else {
            uint2 z2 = make_uint2(0, 0);
            float buf[8];
            uint2 r0 = z2, r1 = z2, r2 = z2, r3 = z2;
            if (Afp) {
                *(float4*)buf = *(const float4*)(Afp + kc);
                *(float4*)(buf+4) = *(const float4*)(Afp + kc + 4);
                r0 = f8_to_fp8(buf, a.ascale);
                *(float4*)buf = *(const float4*)(Afp + kc + 8);
                *(float4*)(buf+4) = *(const float4*)(Afp + kc + 12);
                r1 = f8_to_fp8(buf, a.ascale);
                *(float4*)buf = *(const float4*)(Afp + kc + 16);
                *(float4*)(buf+4) = *(const float4*)(Afp + kc + 20);
                r2 = f8_to_fp8(buf, a.ascale);
                *(float4*)buf = *(const float4*)(Afp + kc + 24);
                *(float4*)(buf+4) = *(const float4*)(Afp + kc + 28);
                r3 = f8_to_fp8(buf, a.ascale);
            }
            uint4 o0 = make_uint4(r0.x, r0.y, r1.x, r1.y);
            uint4 o1 = make_uint4(r2.x, r2.y, r3.x, r3.y);
            *(uint4*)(dAst + st * (int)stageB)      = o0;
            *(uint4*)(dAst + st * (int)stageB + 16) = o1;
        }
    };

    fillA(0, 0);
    cp16(dBl,      Bp,      16);
    cp16(dBl + 16, Bp + 16, 16);
    asm volatile("cp.async.commit_group;" ::: "memory");

    #pragma unroll
    for (int c = 0; c < 4; c++) {
        if (c < 3) {
            int st = (c + 1) & 1;
            int kc = (c + 1) * 64;
            fillA(kc, st);
            cp16(dBl + st * stageB,      Bp + kc,      16);
            cp16(dBl + st * stageB + 16, Bp + kc + 16, 16);
            asm volatile("cp.async.commit_group;" ::: "memory");
            asm volatile("cp.async.wait_group 1;" ::: "memory");
        } else {
            asm volatile("cp.async.wait_group 0;" ::: "memory");
        }
        __syncthreads();

        unsigned aS = aBase + (c & 1) * stageB;
        unsigned bS = bBase + (c & 1) * stageB;
        #pragma unroll
        for (int ks = 0; ks < 2; ks++) {
            unsigned koff = ks * 32u;
            unsigned af[4][4], bfr[4][2];
            #pragma unroll
            for (int mt = 0; mt < 4; mt++)
                LDSM4(af[mt][0], af[mt][1], af[mt][2], af[mt][3],
                      aS + mt * 16u * STRB + koff);
            LDSM4(bfr[0][0], bfr[0][1], bfr[1][0], bfr[1][1], bS + koff);
            LDSM4(bfr[2][0], bfr[2][1], bfr[3][0], bfr[3][1], bS + 16u * STRB + koff);
            #pragma unroll
            for (int mt = 0; mt < 4; mt++)
                #pragma unroll
                for (int nt = 0; nt < 4; nt++) {
                    asm volatile(
                        "mma.sync.aligned.m16n8k32.row.col.f16.e4m3.e4m3.f16 "
                        "{%0,%1}, {%2,%3,%4,%5}, {%6,%7}, {%0,%1};"
                        : "+r"(acc[mt][nt][0]), "+r"(acc[mt][nt][1])
                        : "r"(af[mt][0]), "r"(af[mt][1]), "r"(af[mt][2]), "r"(af[mt][3]),
                          "r"(bfr[nt][0]), "r"(bfr[nt][1]));
                }
        }
        __syncthreads();
    }

    if (a.epi == 1) {
        int base0 = m0 + wm * 64;
        #pragma unroll
        for (int mt = 0; mt < 4; mt++) {
            #pragma unroll
            for (int half = 0; half < 2; half++) {
                int gb = base0 + mt * 16 + half * 8 + ((lane & 16) >> 2);
                bool valid = gb < a.M;
                int r = gb + ((lane >> 2) & 3);
                int rr = valid ? rmap(a, r) : 0;
                #pragma unroll
                for (int nt = 0; nt < 4; nt++) {
                    int col = n0 + wn * 32 + nt * 8 + qc * 2;
                    float o0 = 0.f, o1 = 0.f;
                    if (valid) {
                        float2 p = __half22float2(*(__half2*)&acc[mt][nt][half]);
                        const float* cp = a.Cst + (size_t)rr * 256 + col;
                        o0 = sigt(p.x + __ldg(&a.bias[col]))     * cp[0];
                        o1 = sigt(p.y + __ldg(&a.bias[col + 1])) * cp[1];
                    }
                    o0 += __shfl_xor_sync(0xffffffffu, o0, 4);
                    o0 += __shfl_xor_sync(0xffffffffu, o0, 8);
                    o1 += __shfl_xor_sync(0xffffffffu, o1, 4);
                    o1 += __shfl_xor_sync(0xffffffffu, o1, 8);
                    if (valid && (lane & 12) == 0) {
                        int pr = gb >> 2;
                        *(float2*)((float*)a.Out + (size_t)pr * 256 + col) = make_float2(o0, o1);
                    }
                }
            }
        }
    } else {
        #pragma unroll
        for (int mt = 0; mt < 4; mt++) {
            #pragma unroll
            for (int half = 0; half < 2; half++) {
                int r = m0 + wm * 64 + mt * 16 + qr + half * 8;
                if (r >= a.M) continue;
                #pragma unroll
                for (int nt = 0; nt < 4; nt++) {
                    int col = n0 + wn * 32 + nt * 8 + qc * 2;
                    float2 p = __half22float2(*(__half2*)&acc[mt][nt][half]);
                    if (a.epi == 4) {
                        unsigned short w = f2_to_fp8(p.x * a.oscale, p.y * a.oscale);
                        *(unsigned short*)((u8*)a.Out + (size_t)r * a.Ntot + col) = w;
                    } else {
                        *(float2*)((float*)a.Out + (size_t)r * a.Ntot + col) = make_float2(p.x, p.y);
                    }
                }
            }
        }
    }
}

__global__ __launch_bounds__(256, 3)
void mma_gemm(GemmArgs a0, GemmArgs a1) {
    gemm_body(blockIdx.z ? a1 : a0, blockIdx.x, blockIdx.y);
}

__global__ __launch_bounds__(256, 3)
void level_gemm(GemmArgs f0, GemmArgs f1, GemmArgs u0, GemmArgs u1, int nf) {
    int bid = blockIdx.x;
    if (bid < nf) {
        gemm_body(blockIdx.z ? f1 : f0, bid & 1, bid >> 1);
    } else {
        int r2 = bid - nf;
        gemm_body(blockIdx.z ? u1 : u0, r2 % 6, r2 / 6);
    }
}

// ---------------- weight transpose: S[256,N] fp32 -> D[N,256] fp8 (scaled) ------
struct TPair { const float* s; u8* d; int n; float sc; };
__global__ void transpose_k(TPair p0, TPair p1, TPair p2, TPair p3, TPair p4, TPair p5) {
    TPair p;
    switch (blockIdx.z) {
        case 0: p = p0; break; case 1: p = p1; break; case 2: p = p2; break;
        case 3: p = p3; break; case 4: p = p4; break; default: p = p5; break;
    }
    int x0 = blockIdx.x * 32;
    if (x0 >= p.n) return;
    int y0 = blockIdx.y * 32;
    __shared__ float t[32][33];
    #pragma unroll
    for (int s = 0; s < 32; s += 8)
        t[threadIdx.y + s][threadIdx.x] = p.s[(size_t)(y0 + threadIdx.y + s) * p.n + x0 + threadIdx.x];
    __syncthreads();
    if (threadIdx.x < 16) {
        #pragma unroll
        for (int s = 0; s < 32; s += 8) {
            float v0 = t[2 * threadIdx.x][threadIdx.y + s] * p.sc;
            float v1 = t[2 * threadIdx.x + 1][threadIdx.y + s] * p.sc;
            unsigned short w = f2_to_fp8(v0, v1);
            *(unsigned short*)(p.d + (size_t)(x0 + threadIdx.y + s) * 256 + y0 + 2 * threadIdx.x) = w;
        }
    }
}

// ------- warp-per-leaf: fp8 gather of 8 P rows, f16 accumulate -> activation -----
__global__ __launch_bounds__(256, 5)
void leaf_act_kernel(const int* __restrict__ nf1, const int* __restrict__ nf2,
                     const float* __restrict__ bi1, const float* __restrict__ bi2) {
    int b = blockIdx.z;
    const int* nf = b ? nf2 : nf1;
    const float* bias = b ? bi2 : bi1;
    int warp = threadIdx.x >> 5, lane = threadIdx.x & 31;
    int leaf = blockIdx.x * 8 + warp;
    int tree = leaf >> 8, ll = leaf & 255;
    int gnode = tree * NPT + LEAF_LOC0 + ll;
    int tok = (lane < 8) ? nf[gnode * 8 + lane] : 0;
    unsigned toks[8];
    #pragma unroll
    for (int s = 0; s < 8; s++)
        toks[s] = (unsigned)__shfl_sync(0xffffffffu, tok, s) * 96u;

    const uint2* P = (const uint2*)(g_P8 + (size_t)b * VOCAB * IOUW);
    __half2 acc[3][4];
    #pragma unroll
    for (int k = 0; k < 3; k++) {
        unsigned w = lane + 32u * k;
        #pragma unroll
        for (int p = 0; p < 4; p++) acc[k][p] = __half2(__float2half(0.f), __float2half(0.f));
        #pragma unroll
        for (int s = 0; s < 8; s++) {
            uint2 v = __ldg(P + toks[s] + w);
            acc[k][0] = __hadd2(acc[k][0], fp8_to_h2((unsigned short)(v.x & 0xffffu)));
            acc[k][1] = __hadd2(acc[k][1], fp8_to_h2((unsigned short)(v.x >> 16)));
            acc[k][2] = __hadd2(acc[k][2], fp8_to_h2((unsigned short)(v.y & 0xffffu)));
            acc[k][3] = __hadd2(acc[k][3], fp8_to_h2((unsigned short)(v.y >> 16)));
        }
    }

    const float SC = 0.125f / 32.f;
    int col0 = lane * 8;
    float fi[8], fo[8], fu[8];
    #pragma unroll
    for (int p = 0; p < 4; p++) {
        float2 xi = __half22float2(acc[0][p]);
        float2 xo = __half22float2(acc[1][p]);
        float2 xu = __half22float2(acc[2][p]);
        fi[2*p] = xi.x; fi[2*p+1] = xi.y;
        fo[2*p] = xo.x; fo[2*p+1] = xo.y;
        fu[2*p] = xu.x; fu[2*p+1] = xu.y;
    }
    float4 bi0 = *(const float4*)&bias[col0],       bi1v = *(const float4*)&bias[col0 + 4];
    float4 bo0 = *(const float4*)&bias[256 + col0], bo1v = *(const float4*)&bias[256 + col0 + 4];
    float4 bu0 = *(const float4*)&bias[512 + col0], bu1v = *(const float4*)&bias[512 + col0 + 4];
    float bI[8] = {bi0.x,bi0.y,bi0.z,bi0.w,bi1v.x,bi1v.y,bi1v.z,bi1v.w};
    float bO[8] = {bo0.x,bo0.y,bo0.z,bo0.w,bo1v.x,bo1v.y,bo1v.z,bo1v.w};
    float bU[8] = {bu0.x,bu0.y,bu0.z,bu0.w,bu1v.x,bu1v.y,bu1v.z,bu1v.w};

    float cr[8], hr[8];
    #pragma unroll
    for (int k = 0; k < 8; k++) {
        cr[k] = sigt(fi[k] * SC + bI[k]) * tanh_fast(fu[k] * SC + bU[k]);
        hr[k] = sigt(fo[k] * SC + bO[k]) * tanh_fast(cr[k]);
    }
    size_t base = (size_t)b * NN * HID + (size_t)gnode * HID + col0;
    uint4 hout;
    __nv_bfloat162 h01 = __floats2bfloat162_rn(hr[0], hr[1]);
    __nv_bfloat162 h23 = __floats2bfloat162_rn(hr[2], hr[3]);
    __nv_bfloat162 h45 = __floats2bfloat162_rn(hr[4], hr[5]);
    __nv_bfloat162 h67 = __floats2bfloat162_rn(hr[6], hr[7]);
    hout.x = *(unsigned*)&h01; hout.y = *(unsigned*)&h23;
    hout.z = *(unsigned*)&h45; hout.w = *(unsigned*)&h67;
    *(uint4*)&g_hb[base] = hout;
    *(float4*)&g_c[base]     = make_float4(cr[0], cr[1], cr[2], cr[3]);
    *(float4*)&g_c[base + 4] = make_float4(cr[4], cr[5], cr[6], cr[7]);
    uint2 h8 = f8_to_fp8(hr, 1.f);
    *(uint2*)&g_h8[base] = h8;
}

// ------- act: iou row + single cs row, fp32, writes h (bf16 + fp8) ---------------
__global__ __launch_bounds__(256)
void act_kernel(const float* __restrict__ bi1, const float* __restrict__ bi2,
                int Mp, int start, int rpt) {
    int b = blockIdx.z;
    const float* bias = b ? bi2 : bi1;
    int r = blockIdx.x * 4 + (threadIdx.x >> 6);
    if (r >= Mp) return;
    int j = (threadIdx.x & 63) * 4;
    int tree = r / rpt, lp = r % rpt;
    const float* iou = g_iou + (size_t)b * NINT * IOUW + (size_t)r * IOUW;
    float4 iv = *(const float4*)(iou + j);
    float4 ov = *(const float4*)(iou + 256 + j);
    float4 uv = *(const float4*)(iou + 512 + j);
    float4 bi = *(const float4*)(bias + j);
    float4 bo = *(const float4*)(bias + 256 + j);
    float4 bu = *(const float4*)(bias + 512 + j);
    float4 cs4 = *(const float4*)(g_cs + (size_t)b * NINT * HID + (size_t)r * HID + j);
    float cs[4] = {cs4.x, cs4.y, cs4.z, cs4.w};
    float ivv[4] = {iv.x+bi.x, iv.y+bi.y, iv.z+bi.z, iv.w+bi.w};
    float ovv[4] = {ov.x+bo.x, ov.y+bo.y, ov.z+bo.z, ov.w+bo.w};
    float uvv[4] = {uv.x+bu.x, uv.y+bu.y, uv.z+bu.z, uv.w+bu.w};
    float cr[4], hr[4];
    #pragma unroll
    for (int k = 0; k < 4; k++) {
        cr[k] = sigt(ivv[k]) * tanh_fast(uvv[k]) + cs[k];
        hr[k] = sigt(ovv[k]) * tanh_fast(cr[k]);
    }
    int g = tree * NPT + start + lp;
    size_t base = (size_t)b * NN * HID + (size_t)g * HID + j;
    uint2 hb2;
    __nv_bfloat162 h01 = __floats2bfloat162_rn(hr[0], hr[1]);
    __nv_bfloat162 h23 = __floats2bfloat162_rn(hr[2], hr[3]);
    hb2.x = *(unsigned*)&h01; hb2.y = *(unsigned*)&h23;
    *(uint2*)&g_hb[base] = hb2;
    *(float4*)&g_c[base] = make_float4(cr[0], cr[1], cr[2], cr[3]);
    unsigned short w0 = f2_to_fp8(hr[0], hr[1]);
    unsigned short w1 = f2_to_fp8(hr[2], hr[3]);
    *(unsigned*)&g_h8[base] = (unsigned)w0 | ((unsigned)w1 << 16);
}

// ------- readout phase 1: 8 partial sums per tree --------------------------------
__global__ __launch_bounds__(128)
void readout_part(void) {
    int t = blockIdx.x, part = blockIdx.y, b = blockIdx.z;
    int j = threadIdx.x;
    int n0 = part * 43;
    int n1 = (n0 + 43 < NPT) ? n0 + 43 : NPT;
    const unsigned* hp = (const unsigned*)(g_hb + (size_t)b * NN * HID
                                           + (size_t)t * NPT * HID) + j;
    float s0 = 0.f, s1 = 0.f;
    for (int n = n0; n < n1; n++) {
        float2 v = __bfloat1622float2(*(__nv_bfloat162*)&hp[n * 128]);
        s0 += v.x; s1 += v.y;
    }
    float* dst = g_red + (((size_t)b * T_TREES + t) * 8 + part) * 256 + 2 * j;
    *(float2*)dst = make_float2(s0, s1);
}

// ------- readout phase 2 ---------------------------------------------------------
__global__ __launch_bounds__(256)
void readout_fin(const float* __restrict__ Wf, const float* __restrict__ bf,
                 float* __restrict__ out) {
    int t = blockIdx.x;
    int br = threadIdx.x >> 7;
    int j = threadIdx.x & 127;
    const float* rp = g_red + (((size_t)br * T_TREES + t) * 8) * 256 + 2 * j;
    float s0 = 0.f, s1 = 0.f;
    #pragma unroll
    for (int p = 0; p < 8; p++) {
        float2 v = *(const float2*)(rp + p * 256);
        s0 += v.x; s1 += v.y;
    }
    float m0 = fmaxf(s0 * (1.0f / NPT), 0.f);
    float m1 = fmaxf(s1 * (1.0f / NPT), 0.f);
    int col0 = br * 256 + 2 * j;
    float p0 = m0 * Wf[col0 * 2 + 0] + m1 * Wf[(col0 + 1) * 2 + 0];
    float p1 = m0 * Wf[col0 * 2 + 1] + m1 * Wf[(col0 + 1) * 2 + 1];
    __shared__ float sm0[256], sm1[256];
    sm0[threadIdx.x] = p0; sm1[threadIdx.x] = p1; __syncthreads();
    for (int s = 128; s > 0; s >>= 1) {
        if (threadIdx.x < s) {
            sm0[threadIdx.x] += sm0[threadIdx.x + s];
            sm1[threadIdx.x] += sm1[threadIdx.x + s];
        }
        __syncthreads();
    }
    if (threadIdx.x == 0) {
        float l0 = sm0[0] + bf[0], l1 = sm1[0] + bf[1];
        l0 = (l0 >= 0.f) ? l0 : 0.01f * l0;
        l1 = (l1 >= 0.f) ? l1 : 0.01f * l1;
        float mx = fmaxf(l0, l1);
        float e0 = __expf(l0 - mx), e1 = __expf(l1 - mx);
        float inv = 1.0f / (e0 + e1);
        out[t * 2 + 0] = e0 * inv;
        out[t * 2 + 1] = e1 * inv;
    }
}

// -------------------------------- launch --------------------------------------
extern "C" void kernel_launch(void* const* d_in, const int* in_sizes, int n_in,
                              void* d_out, int out_size) {
    const int*   nf1   = (const int*)  d_in[0];
    const int*   nf2   = (const int*)  d_in[1];
    const float* emb1  = (const float*)d_in[2];
    const float* emb2  = (const float*)d_in[3];
    const float* Wiou1 = (const float*)d_in[4];
    const float* Wiou2 = (const float*)d_in[5];
    const float* Uiou1 = (const float*)d_in[6];
    const float* Uiou2 = (const float*)d_in[7];
    const float* UfW1  = (const float*)d_in[8];
    const float* Ufb1  = (const float*)d_in[9];
    const float* UfW2  = (const float*)d_in[10];
    const float* Ufb2  = (const float*)d_in[11];
    const float* biou1 = (const float*)d_in[12];
    const float* biou2 = (const float*)d_in[13];
    const float* Wf    = (const float*)d_in[14];
    const float* bf    = (const float*)d_in[15];
    float* out = (float*)d_out;

    float *iouS, *c, *cs;
    u8 *P8, *h8, *UfT8, *UiT8, *WiT8;
    bf16 *hb;
    cudaGetSymbolAddress((void**)&P8,   g_P8);
    cudaGetSymbolAddress((void**)&h8,   g_h8);
    cudaGetSymbolAddress((void**)&iouS, g_iou);
    cudaGetSymbolAddress((void**)&c,    g_c);
    cudaGetSymbolAddress((void**)&cs,   g_cs);
    cudaGetSymbolAddress((void**)&hb,   g_hb);
    cudaGetSymbolAddress((void**)&UfT8, g_UfT8);
    cudaGetSymbolAddress((void**)&UiT8, g_UiT8);
    cudaGetSymbolAddress((void**)&WiT8, g_WiT8);

    const size_t Poff = (size_t)VOCAB * IOUW;
    const size_t Hoff = (size_t)NN * HID;
    const size_t Soff = (size_t)NINT * HID;
    const size_t Ioff = (size_t)NINT * IOUW;

    transpose_k<<<dim3(24, 8, 6), dim3(32, 8)>>>(
        TPair{UfW1, UfT8, 256, 1.f},          TPair{UfW2, UfT8 + 256*256, 256, 1.f},
        TPair{Uiou1, UiT8, 768, 1.f},         TPair{Uiou2, UiT8 + 768*256, 768, 1.f},
        TPair{Wiou1, WiT8, 768, 16.f},        TPair{Wiou2, WiT8 + 768*256, 768, 16.f});

    // P tables: emb(fp32 x32 inline) @ Wi(fp8 x16) -> fp8 (stored x32: oscale = 32/512)
    {
        GemmArgs a0{emb1, WiT8,           nullptr, nullptr, P8,        VOCAB, IOUW, 0, 1, 3, 4, 32.f, 0.0625f};
        GemmArgs a1{emb2, WiT8 + 768*256, nullptr, nullptr, P8 + Poff, VOCAB, IOUW, 0, 1, 3, 4, 32.f, 0.0625f};
        mma_gemm<<<dim3(IOUW/128, (VOCAB + 127)/128, 2), 256>>>(a0, a1);
    }
    leaf_act_kernel<<<dim3(NLEAF/8, 1, 2), 256>>>(nf1, nf2, biou1, biou2);

    const int ps_[4]   = {21, 5, 1, 0};
    const int pcnt_[4] = {64, 16, 4, 1};
    const int cs_[4]   = {85, 21, 5, 1};
    const int ccnt_[4] = {256, 64, 16, 4};

    for (int L = 0; L < 4; L++) {
        int Mc = T_TREES * ccnt_[L];
        int Mp = T_TREES * pcnt_[L];
        int nf = 2 * ((Mc + 127) / 128);
        int nu = 6 * ((Mp + 127) / 128);
        GemmArgs f0{h8,        UfT8,           Ufb1, c,        cs,        Mc, 256, cs_[L], ccnt_[L], 1, 1, 1.f, 1.f};
        GemmArgs f1{h8 + Hoff, UfT8 + 256*256, Ufb2, c + Hoff, cs + Soff, Mc, 256, cs_[L], ccnt_[L], 1, 1, 1.f, 1.f};
        GemmArgs u0{hb,        UiT8,           nullptr, nullptr, iouS,        Mp, IOUW, cs_[L], pcnt_[L], 2, 0, 1.f, 1.f};
        GemmArgs u1{hb + Hoff, UiT8 + 768*256, nullptr, nullptr, iouS + Ioff, Mp, IOUW, cs_[L], pcnt_[L], 2, 0, 1.f, 1.f};
        level_gemm<<<dim3(nf + nu, 1, 2), 256>>>(f0, f1, u0, u1, nf);
        act_kernel<<<dim3((Mp + 3)/4, 1, 2), 256>>>(biou1, biou2, Mp, ps_[L], pcnt_[L]);
    }

    readout_part<<<dim3(T_TREES, 8, 2), 128>>>();
    readout_fin<<<T_TREES, 256>>>(Wf, bf, out);
}